// round 15
// baseline (speedup 1.0000x reference)
#include <cuda_runtime.h>
#include <cuda_fp16.h>
#include <cstdint>
#include <math.h>

#define NMAX 100000

// ---------------- device scratch ----------------
__device__ float g_norm2[NMAX];
// fp16 weights: wih0[256x128] | whh0[256x64] | wih1 | whh1 | wih2 | whh2 (each 256x64)
__device__ __align__(16) __half g_w16[114688];

// ---------------- helpers ----------------
__device__ __forceinline__ void mma16(float* c, const unsigned* a, unsigned b0, unsigned b1) {
    asm volatile(
        "mma.sync.aligned.m16n8k16.row.col.f32.f16.f16.f32 "
        "{%0,%1,%2,%3}, {%4,%5,%6,%7}, {%8,%9}, {%0,%1,%2,%3};\n"
        : "+f"(c[0]), "+f"(c[1]), "+f"(c[2]), "+f"(c[3])
        : "r"(a[0]), "r"(a[1]), "r"(a[2]), "r"(a[3]), "r"(b0), "r"(b1));
}
__device__ __forceinline__ float tanha(float x) {
    float y;
    asm("tanh.approx.f32 %0, %1;" : "=f"(y) : "f"(x));
    return y;
}
__device__ __forceinline__ float fsig(float x) {          // sigmoid via 1-MUFU tanh
    return fmaf(0.5f, tanha(0.5f * x), 0.5f);
}
__device__ __forceinline__ float ftanh(float x) {         // accurate tanh (exp-based)
    float a = fabsf(x);
    float e = __expf(-2.0f * a);
    float t = __fdividef(1.0f - e, 1.0f + e);
    return copysignf(t, x);
}
__device__ __forceinline__ uint32_t smem_u32(const void* p) {
    uint32_t a;
    asm("{ .reg .u64 t; cvta.to.shared.u64 t, %1; cvt.u32.u64 %0, t; }" : "=r"(a) : "l"(p));
    return a;
}
__device__ __forceinline__ void cp16(uint32_t dst, const void* src) {
    asm volatile("cp.async.ca.shared.global [%0], [%1], 16;" :: "r"(dst), "l"(src) : "memory");
}
__device__ __forceinline__ void cp_commit() { asm volatile("cp.async.commit_group;" ::: "memory"); }
__device__ __forceinline__ void cp_wait1()  { asm volatile("cp.async.wait_group 1;" ::: "memory"); }
__device__ __forceinline__ void cp_wait0()  { asm volatile("cp.async.wait_group 0;" ::: "memory"); }
__device__ __forceinline__ unsigned h2u(__half2 h) { return *(unsigned*)&h; }

// ---------------- SMEM layout (bytes) ----------------
// A: 128 rows x 200 halves (stride 400B)  -> 51200 B   (K=192 used)
// B: 3-ring x (128 rows x 72 halves = 144B, K=64 chunk) -> 3 x 18432 B
// bsum: 256 floats
#define A_OFF     0
#define B_OFF     51200
#define BBUF_SZ   18432
#define BSUM_OFF  (B_OFF + 3 * BBUF_SZ)    // 106496
#define SMEM_BYTES (BSUM_OFF + 1024)       // 107520

// fp16 weight offsets (in halves): {wih0, whh0, wih1, whh1, wih2, whh2}
__constant__ int c_woff[6] = {0, 32768, 49152, 65536, 81920, 98304};

// ---------------- kernel 1: per-row squared norms + weight fp16 convert ----------------
__global__ void prep_kernel(const float* __restrict__ feat, int n, int nb_norm,
                            const float* __restrict__ wih0, const float* __restrict__ whh0,
                            const float* __restrict__ wih1, const float* __restrict__ whh1,
                            const float* __restrict__ wih2, const float* __restrict__ whh2) {
    if ((int)blockIdx.x < nb_norm) {
        int row = (blockIdx.x * blockDim.x + threadIdx.x) >> 4;
        int sl = threadIdx.x & 15;
        if (row >= n) return;
        float4 v = *(const float4*)(feat + (size_t)row * 64 + sl * 4);
        float s = v.x * v.x + v.y * v.y + v.z * v.z + v.w * v.w;
        #pragma unroll
        for (int o = 8; o; o >>= 1) s += __shfl_down_sync(0xffffffffu, s, o, 16);
        if (sl == 0) g_norm2[row] = s;
    } else {
        int i = (blockIdx.x - nb_norm) * blockDim.x + threadIdx.x;   // one float2 per thread
        if (i >= 57344) return;
        const float* srcs[6] = {wih0, whh0, wih1, whh1, wih2, whh2};
        int reg, off2;
        if (i < 16384) { reg = 0; off2 = i; }
        else { int t = i - 16384; reg = 1 + t / 8192; off2 = t - (reg - 1) * 8192; }
        float2 v = ((const float2*)srcs[reg])[off2];
        int base2 = (reg == 0) ? 0 : (16384 + (reg - 1) * 8192);
        ((__half2*)g_w16)[base2 + off2] = __floats2half2_rn(v.x, v.y);
    }
}

// ---------------- global chunk j -> weight source; stage into ring slot j%3 ----------------
// chunks: l0: j0..2 (p0 c0..2), j3..5 (p1); l1: j6..9; l2: j10..13
__device__ __forceinline__ void stage_chunk(int j, uint32_t sbase, uint32_t bdst_local,
                                            int gP0, int part) {
    int l, jj;
    if (j < 6) { l = 0; jj = j; }
    else if (j < 10) { l = 1; jj = j - 6; }
    else { l = 2; jj = j - 10; }
    const __half* srcw;
    if (l == 0) {
        int p = jj / 3, c = jj % 3;
        if (c < 2) srcw = g_w16 + (size_t)(gP0 + p * 32) * 128 + c * 64 + part * 32;
        else       srcw = g_w16 + 32768 + (size_t)(gP0 + p * 32) * 64 + part * 32;
    } else {
        int p = jj >> 1, c = jj & 1;
        srcw = g_w16 + c_woff[2 * l + c] + (size_t)(gP0 + p * 32) * 64 + part * 32;
    }
    uint32_t dst = sbase + B_OFF + (j % 3) * BBUF_SZ + bdst_local;
    #pragma unroll
    for (int q = 0; q < 4; q++) cp16(dst + q * 16, srcw + q * 8);
    cp_commit();
}

// ---------------- kernel 2: fused gather + 3-layer LSTM (fp16 mma, K64, 3-ring) ----------------
__global__ __launch_bounds__(256, 2) void lstm_kernel(
    const float* __restrict__ feature, const int* __restrict__ src,
    const float* __restrict__ h0, const float* __restrict__ c0,
    const float* __restrict__ bih0, const float* __restrict__ bhh0,
    const float* __restrict__ bih1, const float* __restrict__ bhh1,
    const float* __restrict__ bih2, const float* __restrict__ bhh2,
    float* __restrict__ out, int n)
{
    extern __shared__ char smem[];
    unsigned* Xw = (unsigned*)(smem + A_OFF);        // A as 32-bit words (2 halves each)
    float* bsum = (float*)(smem + BSUM_OFF);
    const uint32_t sbase = smem_u32(smem);

    const int tid = threadIdx.x;
    const int lane = tid & 31;
    const int warp = tid >> 5;
    const int wm = warp >> 1, wn = warp & 1;
    const int gid = lane >> 2, tig = lane & 3;
    const int m0w = wm * 32;
    const int m0 = blockIdx.x * 128;

    // staging role: thread -> (row, 64B half of 128B K64 row)
    const int rp = tid >> 1;
    const int part = tid & 1;
    const int gP0 = (rp >> 5) * 64 + (rp & 31);      // global W row for pass 0
    const uint32_t bdst_local = (uint32_t)(rp * 144 + part * 64);

    const float* bihA[3] = {bih0, bih1, bih2};
    const float* bhhA[3] = {bhh0, bhh1, bhh2};
    const size_t nd = (size_t)n * 64;
    float* out_hs = out + nd;
    float* out_cs = out + 4 * nd;

    // ---- hoisted prologue: stage chunks 0,1 ----
    stage_chunk(0, sbase, bdst_local, gP0, part);
    stage_chunk(1, sbase, bdst_local, gP0, part);

    // ---- inline message passing: per half-warp argmax over 32 neighbors + row gather ----
    {
        const int sl = lane & 15;
        const int seg = lane >> 4;
        #pragma unroll 2
        for (int i = 0; i < 8; i++) {
            const int m = warp * 16 + i * 2 + seg;
            const int node = m0 + m;
            const bool valid = node < n;
            int2 s2 = make_int2(0, 0);
            if (valid) s2 = *(const int2*)(src + (size_t)node * 32 + sl * 2);
            float n0 = g_norm2[s2.x];
            float n1 = g_norm2[s2.y];
            float bv = (n1 > n0) ? n1 : n0;
            int bj = (n1 > n0) ? (2 * sl + 1) : (2 * sl);
            int bs = (n1 > n0) ? s2.y : s2.x;
            #pragma unroll
            for (int o = 8; o; o >>= 1) {
                float ov = __shfl_down_sync(0xffffffffu, bv, o, 16);
                int oj = __shfl_down_sync(0xffffffffu, bj, o, 16);
                int os = __shfl_down_sync(0xffffffffu, bs, o, 16);
                if (ov > bv || (ov == bv && oj < bj)) { bv = ov; bj = oj; bs = os; }
            }
            bs = __shfl_sync(0xffffffffu, bs, 0, 16);
            float4 v = make_float4(0.f, 0.f, 0.f, 0.f);
            if (valid) v = *(const float4*)(feature + (size_t)bs * 64 + sl * 4);
            uint2 t;
            t.x = h2u(__floats2half2_rn(v.x, v.y));
            t.y = h2u(__floats2half2_rn(v.z, v.w));
            *(uint2*)(&Xw[m * 100 + sl * 2]) = t;
        }
    }

    // ---- stage A columns k [64,192): [feature | h0[0]] ----
    #pragma unroll 4
    for (int i = 0; i < 16; i++) {
        int idx = tid + (i << 8);
        int m = idx >> 5, k4 = (idx & 31) + 16;
        int node = m0 + m;
        float4 v = make_float4(0.f, 0.f, 0.f, 0.f);
        if (node < n) {
            size_t off = (size_t)node * 64;
            v = (k4 < 32) ? *(const float4*)(feature + off + (k4 - 16) * 4)
                          : *(const float4*)(h0 + off + (k4 - 32) * 4);
        }
        uint2 t;
        t.x = h2u(__floats2half2_rn(v.x, v.y));
        t.y = h2u(__floats2half2_rn(v.z, v.w));
        *(uint2*)(&Xw[m * 100 + k4 * 2]) = t;
    }

    int gc = 0;   // global chunk counter (0..13)
    for (int l = 0; l < 3; l++) {
        bsum[tid] = bihA[l][tid] + bhhA[l][tid];
        const int ncg = (l == 0) ? 3 : 2;            // K64 chunks per pass

        for (int p = 0; p < 2; p++) {
            float acc[2][8][4];
            #pragma unroll
            for (int mf = 0; mf < 2; mf++)
                #pragma unroll
                for (int f = 0; f < 8; f++)
                    #pragma unroll
                    for (int q = 0; q < 4; q++) acc[mf][f][q] = 0.f;

            #pragma unroll 1
            for (int c = 0; c < ncg; c++) {
                if (gc == 13) cp_wait0(); else cp_wait1();
                __syncthreads();

                const unsigned* Bw = (const unsigned*)(smem + B_OFF + (gc % 3) * BBUF_SZ);
                const int kw = c * 32;                 // chunk base in A words (64 halves)
                #pragma unroll
                for (int ks = 0; ks < 4; ks++) {
                    const int w0 = kw + ks * 8 + tig;
                    unsigned a[2][4];
                    #pragma unroll
                    for (int mf = 0; mf < 2; mf++) {
                        int r = m0w + mf * 16 + gid;
                        a[mf][0] = Xw[r * 100 + w0];
                        a[mf][1] = Xw[(r + 8) * 100 + w0];
                        a[mf][2] = Xw[r * 100 + w0 + 4];
                        a[mf][3] = Xw[(r + 8) * 100 + w0 + 4];
                    }
                    const int bw0 = ks * 8 + tig;
                    #pragma unroll
                    for (int f = 0; f < 8; f++) {
                        int nc = (f >> 1) * 32 + wn * 16 + (f & 1) * 8 + gid;
                        unsigned b0 = Bw[nc * 36 + bw0];
                        unsigned b1 = Bw[nc * 36 + bw0 + 4];
                        mma16(acc[0][f], a[0], b0, b1);
                        mma16(acc[1][f], a[1], b0, b1);
                    }
                }
                // stage chunk gc+2 (ring slot free: all warps passed this chunk's barrier)
                if (gc + 2 < 14) stage_chunk(gc + 2, sbase, bdst_local, gP0, part);
                gc++;
            }

            // ---------------- epilogue for this pass ----------------
            // p==1: barrier first — last chunk's MMA reads of Xw must finish before rebuild
            if (p == 1 && l < 2) __syncthreads();
            {
                const float* cg = c0 + (size_t)l * nd;
                const float* h0n = h0 + (size_t)(l + 1) * nd;
                float* hs_l = out_hs + (size_t)l * nd;
                float* cs_l = out_cs + (size_t)l * nd;

                #pragma unroll
                for (int mf = 0; mf < 2; mf++)
                    #pragma unroll
                    for (int jf = 0; jf < 2; jf++) {
                        const int d0 = p * 32 + wn * 16 + jf * 8 + 2 * tig;
                        #pragma unroll
                        for (int rh = 0; rh < 2; rh++) {
                            const int row = m0w + mf * 16 + gid + rh * 8;
                            const int node = m0 + row;
                            const bool valid = node < n;
                            const size_t noff = (size_t)node * 64;
                            float2 cp2 = make_float2(0.f, 0.f);
                            if (valid) cp2 = *(const float2*)(cg + noff + d0);
                            float hv[2], cv[2];
                            #pragma unroll
                            for (int q = 0; q < 2; q++) {
                                const int pp = rh * 2 + q;
                                const int d = d0 + q;
                                float iv = acc[mf][0 + jf][pp] + bsum[d];
                                float fv = acc[mf][2 + jf][pp] + bsum[64 + d];
                                float gv = acc[mf][4 + jf][pp] + bsum[128 + d];
                                float ov = acc[mf][6 + jf][pp] + bsum[192 + d];
                                float cprev = q ? cp2.y : cp2.x;
                                float cn = fsig(fv) * cprev + fsig(iv) * ftanh(gv);
                                hv[q] = fsig(ov) * ftanh(cn);
                                cv[q] = cn;
                            }
                            if (valid) {
                                *(float2*)(hs_l + noff + d0) = make_float2(hv[0], hv[1]);
                                *(float2*)(cs_l + noff + d0) = make_float2(cv[0], cv[1]);
                                if (l == 2) *(float2*)(out + noff + d0) = make_float2(hv[0], hv[1]);
                            }
                            // A rebuild only after the layer's final pass
                            if (l < 2 && p == 1) {
                                Xw[row * 100 + (d0 >> 1)] = h2u(__floats2half2_rn(hv[0], hv[1]));
                                float2 hh = make_float2(0.f, 0.f);
                                if (valid) hh = *(const float2*)(h0n + noff + d0);
                                Xw[row * 100 + 32 + (d0 >> 1)] = h2u(__floats2half2_rn(hh.x, hh.y));
                                const int dp = d0 - 32;
                                float2 hp = make_float2(0.f, 0.f), h2v = make_float2(0.f, 0.f);
                                if (valid) {
                                    hp = *(const float2*)(hs_l + noff + dp);
                                    h2v = *(const float2*)(h0n + noff + dp);
                                }
                                Xw[row * 100 + (dp >> 1)]      = h2u(__floats2half2_rn(hp.x, hp.y));
                                Xw[row * 100 + 32 + (dp >> 1)] = h2u(__floats2half2_rn(h2v.x, h2v.y));
                            }
                        }
                    }
            }
            // p==1: trailing barrier — Xw rebuild + bsum reads done before next layer
            if (p == 1 && l < 2) __syncthreads();
        }
    }
}

// ---------------- launch ----------------
extern "C" void kernel_launch(void* const* d_in, const int* in_sizes, int n_in,
                              void* d_out, int out_size) {
    const float* feature = (const float*)d_in[0];
    const int* src       = (const int*)d_in[1];
    const float* h0      = (const float*)d_in[2];
    const float* c0      = (const float*)d_in[3];
    const float* wih0    = (const float*)d_in[4];
    const float* whh0    = (const float*)d_in[5];
    const float* bih0    = (const float*)d_in[6];
    const float* bhh0    = (const float*)d_in[7];
    const float* wih1    = (const float*)d_in[8];
    const float* whh1    = (const float*)d_in[9];
    const float* bih1    = (const float*)d_in[10];
    const float* bhh1    = (const float*)d_in[11];
    const float* wih2    = (const float*)d_in[12];
    const float* whh2    = (const float*)d_in[13];
    const float* bih2    = (const float*)d_in[14];
    const float* bhh2    = (const float*)d_in[15];
    float* out = (float*)d_out;

    int n = in_sizes[0] / 64;

    cudaFuncSetAttribute(lstm_kernel, cudaFuncAttributeMaxDynamicSharedMemorySize, SMEM_BYTES);

    int nb_norm = (n * 16 + 255) / 256;
    prep_kernel<<<nb_norm + 224, 256>>>(feature, n, nb_norm,
                                        wih0, whh0, wih1, whh1, wih2, whh2);

    int lblocks = (n + 127) / 128;
    lstm_kernel<<<lblocks, 256, SMEM_BYTES>>>(
        feature, src, h0, c0,
        bih0, bhh0, bih1, bhh1, bih2, bhh2,
        out, n);
}

// round 16
// speedup vs baseline: 1.0750x; 1.0750x over previous
#include <cuda_runtime.h>
#include <cuda_fp16.h>
#include <cstdint>
#include <math.h>

#define NMAX 100000

// ---------------- device scratch ----------------
__device__ float g_norm2[NMAX];
// fp16 weights: wih0[256x128] | whh0[256x64] | wih1 | whh1 | wih2 | whh2 (each 256x64)
__device__ __align__(16) __half g_w16[114688];

// ---------------- helpers ----------------
__device__ __forceinline__ void mma16(float* c, const unsigned* a, unsigned b0, unsigned b1) {
    asm volatile(
        "mma.sync.aligned.m16n8k16.row.col.f32.f16.f16.f32 "
        "{%0,%1,%2,%3}, {%4,%5,%6,%7}, {%8,%9}, {%0,%1,%2,%3};\n"
        : "+f"(c[0]), "+f"(c[1]), "+f"(c[2]), "+f"(c[3])
        : "r"(a[0]), "r"(a[1]), "r"(a[2]), "r"(a[3]), "r"(b0), "r"(b1));
}
__device__ __forceinline__ float tanha(float x) {
    float y;
    asm("tanh.approx.f32 %0, %1;" : "=f"(y) : "f"(x));
    return y;
}
__device__ __forceinline__ float fsig(float x) {          // sigmoid via 1-MUFU tanh
    return fmaf(0.5f, tanha(0.5f * x), 0.5f);
}
__device__ __forceinline__ float ftanh(float x) {         // accurate tanh (exp-based)
    float a = fabsf(x);
    float e = __expf(-2.0f * a);
    float t = __fdividef(1.0f - e, 1.0f + e);
    return copysignf(t, x);
}
__device__ __forceinline__ uint32_t smem_u32(const void* p) {
    uint32_t a;
    asm("{ .reg .u64 t; cvta.to.shared.u64 t, %1; cvt.u32.u64 %0, t; }" : "=r"(a) : "l"(p));
    return a;
}
__device__ __forceinline__ void cp16(uint32_t dst, const void* src) {
    asm volatile("cp.async.ca.shared.global [%0], [%1], 16;" :: "r"(dst), "l"(src) : "memory");
}
__device__ __forceinline__ void cp_commit() { asm volatile("cp.async.commit_group;" ::: "memory"); }
__device__ __forceinline__ void cp_wait1()  { asm volatile("cp.async.wait_group 1;" ::: "memory"); }
__device__ __forceinline__ void cp_wait0()  { asm volatile("cp.async.wait_group 0;" ::: "memory"); }
__device__ __forceinline__ unsigned h2u(__half2 h) { return *(unsigned*)&h; }

// ---------------- SMEM layout (bytes) ----------------
// A: 128 rows x 200 halves (stride 400B)  -> 51200 B   (K=192 used)
// B: 2 buffers x (128 rows x 72 halves = 144B, K=64 chunk) -> 2 x 18432 B
// bsum: 256 floats
#define A_OFF     0
#define B_OFF     51200
#define BBUF_SZ   18432
#define BSUM_OFF  (B_OFF + 2 * BBUF_SZ)    // 88064
#define SMEM_BYTES (BSUM_OFF + 1024)       // 89088

// fp16 weight offsets (in halves): {wih0, whh0, wih1, whh1, wih2, whh2}
__constant__ int c_woff[6] = {0, 32768, 49152, 65536, 81920, 98304};

// ---------------- kernel 1: per-row squared norms + weight fp16 convert ----------------
__global__ void prep_kernel(const float* __restrict__ feat, int n, int nb_norm,
                            const float* __restrict__ wih0, const float* __restrict__ whh0,
                            const float* __restrict__ wih1, const float* __restrict__ whh1,
                            const float* __restrict__ wih2, const float* __restrict__ whh2) {
    if ((int)blockIdx.x < nb_norm) {
        int row = (blockIdx.x * blockDim.x + threadIdx.x) >> 4;
        int sl = threadIdx.x & 15;
        if (row >= n) return;
        float4 v = *(const float4*)(feat + (size_t)row * 64 + sl * 4);
        float s = v.x * v.x + v.y * v.y + v.z * v.z + v.w * v.w;
        #pragma unroll
        for (int o = 8; o; o >>= 1) s += __shfl_down_sync(0xffffffffu, s, o, 16);
        if (sl == 0) g_norm2[row] = s;
    } else {
        int i = (blockIdx.x - nb_norm) * blockDim.x + threadIdx.x;   // one float2 per thread
        if (i >= 57344) return;
        const float* srcs[6] = {wih0, whh0, wih1, whh1, wih2, whh2};
        int reg, off2;
        if (i < 16384) { reg = 0; off2 = i; }
        else { int t = i - 16384; reg = 1 + t / 8192; off2 = t - (reg - 1) * 8192; }
        float2 v = ((const float2*)srcs[reg])[off2];
        int base2 = (reg == 0) ? 0 : (16384 + (reg - 1) * 8192);
        ((__half2*)g_w16)[base2 + off2] = __floats2half2_rn(v.x, v.y);
    }
}

// ---------------- kernel 2: fused gather + 3-layer LSTM (fp16 mma, K64, lean barriers) ----------------
__global__ __launch_bounds__(256, 2) void lstm_kernel(
    const float* __restrict__ feature, const int* __restrict__ src,
    const float* __restrict__ h0, const float* __restrict__ c0,
    const float* __restrict__ bih0, const float* __restrict__ bhh0,
    const float* __restrict__ bih1, const float* __restrict__ bhh1,
    const float* __restrict__ bih2, const float* __restrict__ bhh2,
    float* __restrict__ out, int n)
{
    extern __shared__ char smem[];
    unsigned* Xw = (unsigned*)(smem + A_OFF);        // A as 32-bit words (2 halves each)
    float* bsum = (float*)(smem + BSUM_OFF);
    const uint32_t sbase = smem_u32(smem);

    const int tid = threadIdx.x;
    const int lane = tid & 31;
    const int warp = tid >> 5;
    const int wm = warp >> 1, wn = warp & 1;
    const int gid = lane >> 2, tig = lane & 3;
    const int m0w = wm * 32;
    const int m0 = blockIdx.x * 128;

    // staging role: thread -> (row, 64B half of 128B K64 row)
    const int rp = tid >> 1;
    const int part = tid & 1;
    const int gP0 = (rp >> 5) * 64 + (rp & 31);      // global W row for pass 0
    const uint32_t bdst_local = (uint32_t)(rp * 144 + part * 64);

    const float* bihA[3] = {bih0, bih1, bih2};
    const float* bhhA[3] = {bhh0, bhh1, bhh2};
    const size_t nd = (size_t)n * 64;
    float* out_hs = out + nd;
    float* out_cs = out + 4 * nd;

    // ---- hoisted prologue: stage (l=0,p=0) K64 chunks 0,1 (wih0 k[0,64),[64,128)) ----
    {
        const __half* s0 = g_w16 + (size_t)gP0 * 128 + part * 32;
        uint32_t d0 = sbase + B_OFF + bdst_local;
        #pragma unroll
        for (int q = 0; q < 4; q++) cp16(d0 + q * 16, s0 + q * 8);
        cp_commit();
        const __half* s1 = s0 + 64;
        uint32_t d1 = sbase + B_OFF + BBUF_SZ + bdst_local;
        #pragma unroll
        for (int q = 0; q < 4; q++) cp16(d1 + q * 16, s1 + q * 8);
        cp_commit();
    }

    // ---- inline message passing: per half-warp argmax over 32 neighbors + row gather ----
    {
        const int sl = lane & 15;
        const int seg = lane >> 4;
        #pragma unroll 2
        for (int i = 0; i < 8; i++) {
            const int m = warp * 16 + i * 2 + seg;
            const int node = m0 + m;
            const bool valid = node < n;
            int2 s2 = make_int2(0, 0);
            if (valid) s2 = *(const int2*)(src + (size_t)node * 32 + sl * 2);
            float n0 = g_norm2[s2.x];
            float n1 = g_norm2[s2.y];
            float bv = (n1 > n0) ? n1 : n0;
            int bj = (n1 > n0) ? (2 * sl + 1) : (2 * sl);
            int bs = (n1 > n0) ? s2.y : s2.x;
            #pragma unroll
            for (int o = 8; o; o >>= 1) {
                float ov = __shfl_down_sync(0xffffffffu, bv, o, 16);
                int oj = __shfl_down_sync(0xffffffffu, bj, o, 16);
                int os = __shfl_down_sync(0xffffffffu, bs, o, 16);
                if (ov > bv || (ov == bv && oj < bj)) { bv = ov; bj = oj; bs = os; }
            }
            bs = __shfl_sync(0xffffffffu, bs, 0, 16);
            float4 v = make_float4(0.f, 0.f, 0.f, 0.f);
            if (valid) v = *(const float4*)(feature + (size_t)bs * 64 + sl * 4);
            uint2 t;
            t.x = h2u(__floats2half2_rn(v.x, v.y));
            t.y = h2u(__floats2half2_rn(v.z, v.w));
            *(uint2*)(&Xw[m * 100 + sl * 2]) = t;
        }
    }

    // ---- stage A columns k [64,192): [feature | h0[0]] ----
    #pragma unroll 4
    for (int i = 0; i < 16; i++) {
        int idx = tid + (i << 8);
        int m = idx >> 5, k4 = (idx & 31) + 16;
        int node = m0 + m;
        float4 v = make_float4(0.f, 0.f, 0.f, 0.f);
        if (node < n) {
            size_t off = (size_t)node * 64;
            v = (k4 < 32) ? *(const float4*)(feature + off + (k4 - 16) * 4)
                          : *(const float4*)(h0 + off + (k4 - 32) * 4);
        }
        uint2 t;
        t.x = h2u(__floats2half2_rn(v.x, v.y));
        t.y = h2u(__floats2half2_rn(v.z, v.w));
        *(uint2*)(&Xw[m * 100 + k4 * 2]) = t;
    }

    for (int l = 0; l < 3; l++) {
        bsum[tid] = bihA[l][tid] + bhhA[l][tid];
        const int ncg = (l == 0) ? 3 : 2;            // K64 chunks per pass

        for (int p = 0; p < 2; p++) {
            const int grow = gP0 + p * 32;

            // prologue staging of chunks 0,1 (skip l=0,p=0: hoisted)
            if (!(l == 0 && p == 0)) {
                #pragma unroll 1
                for (int c = 0; c < 2; c++) {
                    const __half* wp; int rs, ko;
                    if (l == 0) { wp = g_w16 + c_woff[0]; rs = 128; ko = c * 64; }
                    else {
                        int reg = (c == 0) ? (2 * l) : (2 * l + 1);
                        wp = g_w16 + c_woff[reg]; rs = 64; ko = 0;
                    }
                    const __half* srcw = wp + (size_t)grow * rs + ko + part * 32;
                    uint32_t dst = sbase + B_OFF + (c & 1) * BBUF_SZ + bdst_local;
                    #pragma unroll
                    for (int q = 0; q < 4; q++) cp16(dst + q * 16, srcw + q * 8);
                    cp_commit();
                }
            }

            float acc[2][8][4];
            #pragma unroll
            for (int mf = 0; mf < 2; mf++)
                #pragma unroll
                for (int f = 0; f < 8; f++)
                    #pragma unroll
                    for (int q = 0; q < 4; q++) acc[mf][f][q] = 0.f;

            #pragma unroll 1
            for (int c = 0; c < ncg; c++) {
                if (c < ncg - 1) cp_wait1(); else cp_wait0();
                __syncthreads();

                const unsigned* Bw = (const unsigned*)(smem + B_OFF + (c & 1) * BBUF_SZ);
                const int kw = c * 32;                 // chunk base in A words (64 halves)
                #pragma unroll
                for (int ks = 0; ks < 4; ks++) {
                    const int w0 = kw + ks * 8 + tig;
                    unsigned a[2][4];
                    #pragma unroll
                    for (int mf = 0; mf < 2; mf++) {
                        int r = m0w + mf * 16 + gid;
                        a[mf][0] = Xw[r * 100 + w0];
                        a[mf][1] = Xw[(r + 8) * 100 + w0];
                        a[mf][2] = Xw[r * 100 + w0 + 4];
                        a[mf][3] = Xw[(r + 8) * 100 + w0 + 4];
                    }
                    const int bw0 = ks * 8 + tig;
                    #pragma unroll
                    for (int f = 0; f < 8; f++) {
                        int nc = (f >> 1) * 32 + wn * 16 + (f & 1) * 8 + gid;
                        unsigned b0 = Bw[nc * 36 + bw0];
                        unsigned b1 = Bw[nc * 36 + bw0 + 4];
                        mma16(acc[0][f], a[0], b0, b1);
                        mma16(acc[1][f], a[1], b0, b1);
                    }
                }
                // re-stage chunk c+2 into buffer (c+2)&1 (only l=0: chunk 2 = whh0);
                // barrier ONLY here — it overwrites the buffer just read
                int c2 = c + 2;
                if (c2 < ncg) {
                    __syncthreads();
                    const __half* srcw = g_w16 + c_woff[1] + (size_t)grow * 64 + part * 32;
                    uint32_t dst = sbase + B_OFF + (c2 & 1) * BBUF_SZ + bdst_local;
                    #pragma unroll
                    for (int q = 0; q < 4; q++) cp16(dst + q * 16, srcw + q * 8);
                    cp_commit();
                }
            }
            // end-of-pass sync: all warps done reading B buffers (next pass restages them)
            // and done reading Xw (p==1 epilogue rebuilds it). Skip on very last pass.
            if (!(l == 2 && p == 1)) __syncthreads();

            // ---------------- epilogue for this pass ----------------
            {
                const float* cg = c0 + (size_t)l * nd;
                const float* h0n = h0 + (size_t)(l + 1) * nd;
                float* hs_l = out_hs + (size_t)l * nd;
                float* cs_l = out_cs + (size_t)l * nd;

                #pragma unroll
                for (int mf = 0; mf < 2; mf++)
                    #pragma unroll
                    for (int jf = 0; jf < 2; jf++) {
                        const int d0 = p * 32 + wn * 16 + jf * 8 + 2 * tig;
                        #pragma unroll
                        for (int rh = 0; rh < 2; rh++) {
                            const int row = m0w + mf * 16 + gid + rh * 8;
                            const int node = m0 + row;
                            const bool valid = node < n;
                            const size_t noff = (size_t)node * 64;
                            float2 cp2 = make_float2(0.f, 0.f);
                            if (valid) cp2 = *(const float2*)(cg + noff + d0);
                            float hv[2], cv[2];
                            #pragma unroll
                            for (int q = 0; q < 2; q++) {
                                const int pp = rh * 2 + q;
                                const int d = d0 + q;
                                float iv = acc[mf][0 + jf][pp] + bsum[d];
                                float fv = acc[mf][2 + jf][pp] + bsum[64 + d];
                                float gv = acc[mf][4 + jf][pp] + bsum[128 + d];
                                float ov = acc[mf][6 + jf][pp] + bsum[192 + d];
                                float cprev = q ? cp2.y : cp2.x;
                                float cn = fsig(fv) * cprev + fsig(iv) * ftanh(gv);
                                hv[q] = fsig(ov) * ftanh(cn);
                                cv[q] = cn;
                            }
                            if (valid) {
                                *(float2*)(hs_l + noff + d0) = make_float2(hv[0], hv[1]);
                                *(float2*)(cs_l + noff + d0) = make_float2(cv[0], cv[1]);
                                if (l == 2) *(float2*)(out + noff + d0) = make_float2(hv[0], hv[1]);
                            }
                            // A rebuild only after the layer's final pass (end-of-pass sync
                            // above guarantees all MMA reads of Xw are complete)
                            if (l < 2 && p == 1) {
                                Xw[row * 100 + (d0 >> 1)] = h2u(__floats2half2_rn(hv[0], hv[1]));
                                float2 hh = make_float2(0.f, 0.f);
                                if (valid) hh = *(const float2*)(h0n + noff + d0);
                                Xw[row * 100 + 32 + (d0 >> 1)] = h2u(__floats2half2_rn(hh.x, hh.y));
                                const int dp = d0 - 32;
                                float2 hp = make_float2(0.f, 0.f), h2v = make_float2(0.f, 0.f);
                                if (valid) {
                                    hp = *(const float2*)(hs_l + noff + dp);
                                    h2v = *(const float2*)(h0n + noff + dp);
                                }
                                Xw[row * 100 + (dp >> 1)]      = h2u(__floats2half2_rn(hp.x, hp.y));
                                Xw[row * 100 + 32 + (dp >> 1)] = h2u(__floats2half2_rn(h2v.x, h2v.y));
                            }
                        }
                    }
            }
            // trailing sync only where the next layer overwrites bsum / reads rebuilt Xw
            if (p == 1 && l < 2) __syncthreads();
        }
    }
}

// ---------------- launch ----------------
extern "C" void kernel_launch(void* const* d_in, const int* in_sizes, int n_in,
                              void* d_out, int out_size) {
    const float* feature = (const float*)d_in[0];
    const int* src       = (const int*)d_in[1];
    const float* h0      = (const float*)d_in[2];
    const float* c0      = (const float*)d_in[3];
    const float* wih0    = (const float*)d_in[4];
    const float* whh0    = (const float*)d_in[5];
    const float* bih0    = (const float*)d_in[6];
    const float* bhh0    = (const float*)d_in[7];
    const float* wih1    = (const float*)d_in[8];
    const float* whh1    = (const float*)d_in[9];
    const float* bih1    = (const float*)d_in[10];
    const float* bhh1    = (const float*)d_in[11];
    const float* wih2    = (const float*)d_in[12];
    const float* whh2    = (const float*)d_in[13];
    const float* bih2    = (const float*)d_in[14];
    const float* bhh2    = (const float*)d_in[15];
    float* out = (float*)d_out;

    int n = in_sizes[0] / 64;

    cudaFuncSetAttribute(lstm_kernel, cudaFuncAttributeMaxDynamicSharedMemorySize, SMEM_BYTES);

    int nb_norm = (n * 16 + 255) / 256;
    prep_kernel<<<nb_norm + 224, 256>>>(feature, n, nb_norm,
                                        wih0, whh0, wih1, whh1, wih2, whh2);

    int lblocks = (n + 127) / 128;
    lstm_kernel<<<lblocks, 256, SMEM_BYTES>>>(
        feature, src, h0, c0,
        bih0, bhh0, bih1, bhh1, bih2, bhh2,
        out, n);
}